// round 14
// baseline (speedup 1.0000x reference)
#include <cuda_runtime.h>
#include <cuda_fp16.h>

#define NU 100000
#define NE 100000
#define NN 200000
#define C  64
#define N_HOPS 3
#define NT (NE + NN + NU)            // combined destination space
#define MAXREC 4000000               // E + E2 + NNZ
#define SCAN_BLK 1024
#define NB ((NT + SCAN_BLK - 1) / SCAN_BLK)

// -------- persistent scratch (static device globals) --------
__device__ __align__(16) __half g_all0[(size_t)NN * C];  // ping (fp16)
__device__ __align__(16) __half g_all1[(size_t)NN * C];  // pong (fp16)
__device__ __align__(16) __half g_wh[32 * C];            // combined weight tables (fp16)
__device__ __align__(16) float  g_f[2 * NE];             // ||sum||/cnt, double-buffered
__device__ int   g_cnt[NT];
__device__ int   g_rowptr[NT + 1];
__device__ int   g_cursor[NT];
__device__ unsigned long long g_scan_state[NB];          // (val<<2)|status for lookback
__device__ int   g_reci[MAXREC];                         // packed edge recs (head region)
__device__ __align__(16) int2 g_rec2[1000000];           // im recs {col, valbits} (CSR tail)

// buffer written by gather hop h (h = -1 means the initial embedding buffer)
__device__ __forceinline__ const __half* buf_of(int h) {
    return (h & 1) ? g_all0 : g_all1;
}
__device__ __forceinline__ __half* buf_of_mut(int h) {
    return (h & 1) ? g_all0 : g_all1;
}

// ---------------------------------------------------------------------------
// zero g_cnt + scan state
// ---------------------------------------------------------------------------
__global__ void zero_cnt_kernel() {
    int i = blockIdx.x * blockDim.x + threadIdx.x;
    if (i < NT / 4) ((int4*)g_cnt)[i] = make_int4(0, 0, 0, 0);
    if (i < NB) g_scan_state[i] = 0ULL;
}

// ---------------------------------------------------------------------------
// merged init + hist
// ---------------------------------------------------------------------------
__global__ void init_hist_kernel(const float* __restrict__ user_emb,
                                 const float* __restrict__ entity_emb,
                                 const float* __restrict__ w,
                                 const float* __restrict__ w2,
                                 const int* __restrict__ ei,
                                 const int* __restrict__ e2i,
                                 const int* __restrict__ im_row,
                                 int E, int E2, int NNZ) {
    const size_t rec_n = (size_t)E + E2 + NNZ;
    const size_t nn4   = (size_t)NN * C / 4;
    const size_t nu4   = (size_t)NU * C / 4;
    const size_t total = rec_n + nn4 + 31 * C;
    uint2*        all2 = (uint2*)g_all0;
    const float4* ue4  = (const float4*)user_emb;
    const float4* ee4  = (const float4*)entity_emb;
    for (size_t i = (size_t)blockIdx.x * blockDim.x + threadIdx.x;
         i < total; i += (size_t)gridDim.x * blockDim.x) {
        if (i < rec_n) {
            int d;
            if (i < (size_t)E)            d = ei[i];
            else if (i < (size_t)E + E2)  d = NE + e2i[i - E];
            else                          d = NE + NN + im_row[i - E - E2];
            atomicAdd(g_cnt + d, 1);
        } else if (i < rec_n + nn4) {
            size_t j = i - rec_n;
            float4 v = (j < nu4) ? ue4[j] : ee4[j - nu4];
            uint2 h;
            *(__half2*)&h.x = __floats2half2_rn(v.x, v.y);
            *(__half2*)&h.y = __floats2half2_rn(v.z, v.w);
            all2[j] = h;
        } else {
            size_t j = i - rec_n - nn4;
            float x = (j < 15 * C) ? w[j] : w2[j - 15 * C];
            g_wh[j] = __float2half_rn(x);
        }
    }
}

// ---------------------------------------------------------------------------
// single-kernel decoupled-lookback scan: g_cnt -> g_rowptr (+cursor)
// ---------------------------------------------------------------------------
__global__ void scan_lb_kernel(int total_rec) {
    __shared__ int s[256];
    __shared__ int s_prefix;
    int tid  = threadIdx.x;
    int b    = blockIdx.x;
    int base = b * SCAN_BLK + tid * 4;
    int v[4], t = 0;
    #pragma unroll
    for (int k = 0; k < 4; k++) {
        v[k] = (base + k < NT) ? g_cnt[base + k] : 0;
        t += v[k];
    }
    s[tid] = t;
    __syncthreads();
    #pragma unroll
    for (int off = 1; off < 256; off <<= 1) {
        int x = (tid >= off) ? s[tid - off] : 0;
        __syncthreads();
        s[tid] += x;
        __syncthreads();
    }
    int incl_local = s[tid];
    if (tid == 0) {
        int block_total = s[255];
        atomicExch(&g_scan_state[b],
                   ((unsigned long long)(unsigned)block_total << 2) | 1ULL);
        int prefix = 0;
        for (int j = b - 1; j >= 0; j--) {
            unsigned long long st;
            do { st = atomicAdd(&g_scan_state[j], 0ULL); } while ((st & 3ULL) == 0ULL);
            prefix += (int)(unsigned)(st >> 2);
            if ((st & 3ULL) == 2ULL) break;
        }
        atomicExch(&g_scan_state[b],
                   ((unsigned long long)(unsigned)(prefix + block_total) << 2) | 2ULL);
        s_prefix = prefix;
        if (b == 0) g_rowptr[NT] = total_rec;
    }
    __syncthreads();
    int run = s_prefix + incl_local - t;    // global exclusive prefix
    #pragma unroll
    for (int k = 0; k < 4; k++) {
        if (base + k < NT) { g_rowptr[base + k] = run; g_cursor[base + k] = run; }
        run += v[k];
    }
}

// ---------------------------------------------------------------------------
// fill: 4 records per thread (MLP=4). Edge recs -> one 4B write;
// im recs -> one 8B int2 write (col, valbits) in the CSR tail.
// ---------------------------------------------------------------------------
__global__ void __launch_bounds__(256) fill_kernel(
    const int* __restrict__ ei,  const int* __restrict__ ety,
    const int* __restrict__ e2i, const int* __restrict__ e2ty,
    const int* __restrict__ im_row, const int* __restrict__ im_col,
    const float* __restrict__ im_val,
    int E, int E2, int NNZ)
{
    int total = E + E2 + NNZ;
    int EE2   = E + E2;
    int base  = (blockIdx.x * blockDim.x + threadIdx.x) * 4;
    if (base >= total) return;

    int  d[4], ival[4], ival2[4];
    bool valid[4], is_im[4];
    #pragma unroll
    for (int k = 0; k < 4; k++) {
        int i = base + k;
        valid[k] = (i < total);
        d[k] = 0; ival[k] = 0; ival2[k] = 0; is_im[k] = false;
        if (!valid[k]) continue;
        if (i < E) {
            d[k]    = ei[i];
            ival[k] = (NU + ei[E + i]) * 32 + (ety[i] - 1);
        } else if (i < EE2) {
            int e2  = i - E;
            d[k]    = NE + e2i[e2];
            ival[k] = e2i[E2 + e2] * 32 + (15 + e2ty[e2]);
        } else {
            int j    = i - EE2;
            d[k]     = NE + NN + im_row[j];
            ival[k]  = im_col[j];
            ival2[k] = __float_as_int(im_val[j]);
            is_im[k] = true;
        }
    }
    int pos[4];
    #pragma unroll
    for (int k = 0; k < 4; k++)
        if (valid[k]) pos[k] = atomicAdd(g_cursor + d[k], 1);
    #pragma unroll
    for (int k = 0; k < 4; k++) {
        if (!valid[k]) continue;
        if (is_im[k]) g_rec2[pos[k] - EE2] = make_int2(ival[k], ival2[k]);
        else          g_reci[pos[k]]       = ival[k];
    }
}

// ---------------------------------------------------------------------------
// fused per-hop kernel: 8-lane group per destination row (R12 structure)
// ---------------------------------------------------------------------------
__device__ __forceinline__ float grp_sum8(float s) {
    #pragma unroll
    for (int o = 4; o; o >>= 1) s += __shfl_xor_sync(0xffffffffu, s, o);
    return s;
}

struct F8 { float4 a, b; };

__device__ __forceinline__ F8 h8_to_f8(uint4 h) {
    F8 r;
    float2 p0 = __half22float2(*(__half2*)&h.x);
    float2 p1 = __half22float2(*(__half2*)&h.y);
    float2 p2 = __half22float2(*(__half2*)&h.z);
    float2 p3 = __half22float2(*(__half2*)&h.w);
    r.a = make_float4(p0.x, p0.y, p1.x, p1.y);
    r.b = make_float4(p2.x, p2.y, p3.x, p3.y);
    return r;
}

__global__ void __launch_bounds__(256) fused_kernel(
    int hop_g, int do_g, int hop_m, int do_m, int base, int EE2,
    const float* __restrict__ user_emb, const float* __restrict__ entity_emb,
    float* __restrict__ node_res, float* __restrict__ ent_out,
    float* __restrict__ user_res)
{
    int gidx = base + ((blockIdx.x * blockDim.x + threadIdx.x) >> 3);
    int lane = threadIdx.x & 7;

    if (gidx < NE + NN) {
        // ---------------- gather path (hop_g) ----------------
        if (!do_g) return;
        const __half* prev = buf_of(hop_g - 1);
        __half*       next = buf_of_mut(hop_g);
        float*        fdst = g_f + (hop_g & 1) * NE;
        int hop0 = (hop_g == 0);

        int start = g_rowptr[gidx], end = g_rowptr[gidx + 1];
        float4 accA = make_float4(0.f, 0.f, 0.f, 0.f);
        float4 accB = make_float4(0.f, 0.f, 0.f, 0.f);
        int e = start;
        for (; e + 1 < end; e += 2) {
            int r0 = __ldg(g_reci + e);
            int r1 = __ldg(g_reci + e + 1);
            uint4 h0 = *((const uint4*)(prev + (size_t)(r0 >> 5) * C) + lane);
            uint4 h1 = *((const uint4*)(prev + (size_t)(r1 >> 5) * C) + lane);
            uint4 wh0 = *((const uint4*)(g_wh + (r0 & 31) * C) + lane);
            uint4 wh1 = *((const uint4*)(g_wh + (r1 & 31) * C) + lane);
            F8 s0 = h8_to_f8(h0), s1 = h8_to_f8(h1);
            F8 w0 = h8_to_f8(wh0), w1 = h8_to_f8(wh1);
            accA.x += s0.a.x * w0.a.x + s1.a.x * w1.a.x;
            accA.y += s0.a.y * w0.a.y + s1.a.y * w1.a.y;
            accA.z += s0.a.z * w0.a.z + s1.a.z * w1.a.z;
            accA.w += s0.a.w * w0.a.w + s1.a.w * w1.a.w;
            accB.x += s0.b.x * w0.b.x + s1.b.x * w1.b.x;
            accB.y += s0.b.y * w0.b.y + s1.b.y * w1.b.y;
            accB.z += s0.b.z * w0.b.z + s1.b.z * w1.b.z;
            accB.w += s0.b.w * w0.b.w + s1.b.w * w1.b.w;
        }
        if (e < end) {
            int r0 = __ldg(g_reci + e);
            uint4 h0 = *((const uint4*)(prev + (size_t)(r0 >> 5) * C) + lane);
            uint4 wh0 = *((const uint4*)(g_wh + (r0 & 31) * C) + lane);
            F8 s0 = h8_to_f8(h0);
            F8 w0 = h8_to_f8(wh0);
            accA.x += s0.a.x * w0.a.x; accA.y += s0.a.y * w0.a.y;
            accA.z += s0.a.z * w0.a.z; accA.w += s0.a.w * w0.a.w;
            accB.x += s0.b.x * w0.b.x; accB.y += s0.b.y * w0.b.y;
            accB.z += s0.b.z * w0.b.z; accB.w += s0.b.w * w0.b.w;
        }

        float ss = grp_sum8(accA.x * accA.x + accA.y * accA.y + accA.z * accA.z + accA.w * accA.w
                          + accB.x * accB.x + accB.y * accB.y + accB.z * accB.z + accB.w * accB.w);
        float n  = sqrtf(ss);
        float inv = 1.0f / fmaxf(n, 1e-12f);
        float4 oa = make_float4(accA.x * inv, accA.y * inv, accA.z * inv, accA.w * inv);
        float4 ob = make_float4(accB.x * inv, accB.y * inv, accB.z * inv, accB.w * inv);
        uint4 oh;
        *(__half2*)&oh.x = __floats2half2_rn(oa.x, oa.y);
        *(__half2*)&oh.y = __floats2half2_rn(oa.z, oa.w);
        *(__half2*)&oh.z = __floats2half2_rn(ob.x, ob.y);
        *(__half2*)&oh.w = __floats2half2_rn(ob.z, ob.w);

        if (gidx < NE) {
            *((uint4*)(next + (size_t)(NU + gidx) * C) + lane) = oh;
            if (lane == 0) fdst[gidx] = n / fmaxf((float)(end - start), 1.0f);
            if (hop_g == N_HOPS - 1) {
                float4* op = (float4*)(ent_out + (size_t)gidx * C) + lane * 2;
                op[0] = oa; op[1] = ob;
            }
        } else {
            int r = gidx - NE;
            if (r < NU) *((uint4*)(next + (size_t)r * C) + lane) = oh;
            float4* rp = (float4*)(node_res + (size_t)r * C) + lane * 2;
            float4 a0, a1;
            if (hop0) {
                const float4* ip = (r < NU)
                    ? (const float4*)(user_emb + (size_t)r * C) + lane * 2
                    : (const float4*)(entity_emb + (size_t)(r - NU) * C) + lane * 2;
                a0 = ip[0]; a1 = ip[1];
            } else {
                a0 = rp[0]; a1 = rp[1];
            }
            a0.x += oa.x; a0.y += oa.y; a0.z += oa.z; a0.w += oa.w;
            a1.x += ob.x; a1.y += ob.y; a1.z += ob.z; a1.w += ob.w;
            rp[0] = a0; rp[1] = a1;
        }
    } else if (gidx < NT) {
        // ---------------- im path (hop_m) ----------------
        if (!do_m) return;
        const __half* src  = buf_of(hop_m);
        const float*  fsrc = g_f + (hop_m & 1) * NE;
        int hop0 = (hop_m == 0);
        int u = gidx - NE - NN;

        int start = g_rowptr[gidx], end = g_rowptr[gidx + 1];
        float4 accA = make_float4(0.f, 0.f, 0.f, 0.f);
        float4 accB = make_float4(0.f, 0.f, 0.f, 0.f);
        int e = start;
        for (; e + 1 < end; e += 2) {
            int2 r0 = __ldg(g_rec2 + (e - EE2));
            int2 r1 = __ldg(g_rec2 + (e + 1 - EE2));
            float c0 = __int_as_float(r0.y) * __ldg(fsrc + r0.x);
            float c1 = __int_as_float(r1.y) * __ldg(fsrc + r1.x);
            uint4 h0 = *((const uint4*)(src + (size_t)(NU + r0.x) * C) + lane);
            uint4 h1 = *((const uint4*)(src + (size_t)(NU + r1.x) * C) + lane);
            F8 s0 = h8_to_f8(h0);
            F8 s1 = h8_to_f8(h1);
            accA.x += s0.a.x * c0 + s1.a.x * c1;
            accA.y += s0.a.y * c0 + s1.a.y * c1;
            accA.z += s0.a.z * c0 + s1.a.z * c1;
            accA.w += s0.a.w * c0 + s1.a.w * c1;
            accB.x += s0.b.x * c0 + s1.b.x * c1;
            accB.y += s0.b.y * c0 + s1.b.y * c1;
            accB.z += s0.b.z * c0 + s1.b.z * c1;
            accB.w += s0.b.w * c0 + s1.b.w * c1;
        }
        if (e < end) {
            int2 r0 = __ldg(g_rec2 + (e - EE2));
            float c0 = __int_as_float(r0.y) * __ldg(fsrc + r0.x);
            uint4 h0 = *((const uint4*)(src + (size_t)(NU + r0.x) * C) + lane);
            F8 s0 = h8_to_f8(h0);
            accA.x += s0.a.x * c0; accA.y += s0.a.y * c0;
            accA.z += s0.a.z * c0; accA.w += s0.a.w * c0;
            accB.x += s0.b.x * c0; accB.y += s0.b.y * c0;
            accB.z += s0.b.z * c0; accB.w += s0.b.w * c0;
        }

        float ss = grp_sum8(accA.x * accA.x + accA.y * accA.y + accA.z * accA.z + accA.w * accA.w
                          + accB.x * accB.x + accB.y * accB.y + accB.z * accB.z + accB.w * accB.w);
        float inv = 1.0f / fmaxf(sqrtf(ss), 1e-12f);
        float4* rp = (float4*)(user_res + (size_t)u * C) + lane * 2;
        float4 a0, a1;
        if (hop0) {
            const float4* ip = (const float4*)(user_emb + (size_t)u * C) + lane * 2;
            a0 = ip[0]; a1 = ip[1];
        } else {
            a0 = rp[0]; a1 = rp[1];
        }
        a0.x += accA.x * inv; a0.y += accA.y * inv;
        a0.z += accA.z * inv; a0.w += accA.w * inv;
        a1.x += accB.x * inv; a1.y += accB.y * inv;
        a1.z += accB.z * inv; a1.w += accB.w * inv;
        rp[0] = a0; rp[1] = a1;
    }
}

// ---------------------------------------------------------------------------
extern "C" void kernel_launch(void* const* d_in, const int* in_sizes, int n_in,
                              void* d_out, int out_size) {
    const float* user_emb     = (const float*)d_in[0];
    const float* entity_emb   = (const float*)d_in[1];
    const float* weight       = (const float*)d_in[2];
    const float* extra_weight = (const float*)d_in[3];
    const float* im_val       = (const float*)d_in[4];
    const int*   edge_index   = (const int*)d_in[5];
    const int*   edge_type    = (const int*)d_in[6];
    const int*   extra_eidx   = (const int*)d_in[7];
    const int*   extra_etype  = (const int*)d_in[8];
    const int*   im_row       = (const int*)d_in[9];
    const int*   im_col       = (const int*)d_in[10];

    const int E   = in_sizes[6];
    const int E2  = in_sizes[8];
    const int NNZ = in_sizes[4];
    const int total_rec = E + E2 + NNZ;
    const int EE2 = E + E2;

    float* out      = (float*)d_out;
    float* user_res = out;                      // [NU, C]
    float* ent_out  = out + (size_t)NU * C;     // [NE, C]
    float* node_res = out + (size_t)NN * C;     // [NN, C]

    zero_cnt_kernel<<<(NT / 4 + 255) / 256, 256>>>();
    init_hist_kernel<<<2048, 256>>>(user_emb, entity_emb, weight, extra_weight,
                                    edge_index, extra_eidx, im_row, E, E2, NNZ);
    scan_lb_kernel<<<NB, 256>>>(total_rec);
    fill_kernel<<<(total_rec + 1023) / 1024, 256>>>(edge_index, edge_type,
                                                    extra_eidx, extra_etype,
                                                    im_row, im_col, im_val, E, E2, NNZ);

    const int g_blocks  = ((NE + NN) * 8 + 255) / 256;   // gather-only
    const int gm_blocks = (NT * 8 + 255) / 256;          // gather + im
    const int m_blocks  = (NU * 8 + 255) / 256;          // im-only

    // g0 ; [im0 || g1] ; [im1 || g2] ; im2
    fused_kernel<<<g_blocks, 256>>>(0, 1, 0, 0, 0, EE2,
                                    user_emb, entity_emb, node_res, ent_out, user_res);
    fused_kernel<<<gm_blocks, 256>>>(1, 1, 0, 1, 0, EE2,
                                     user_emb, entity_emb, node_res, ent_out, user_res);
    fused_kernel<<<gm_blocks, 256>>>(2, 1, 1, 1, 0, EE2,
                                     user_emb, entity_emb, node_res, ent_out, user_res);
    fused_kernel<<<m_blocks, 256>>>(0, 0, 2, 1, NE + NN, EE2,
                                    user_emb, entity_emb, node_res, ent_out, user_res);
}

// round 15
// speedup vs baseline: 1.0527x; 1.0527x over previous
#include <cuda_runtime.h>
#include <cuda_fp16.h>

#define NU 100000
#define NE 100000
#define NN 200000
#define C  64
#define N_HOPS 3
#define NT (NE + NN + NU)            // combined destination space
#define MAXREC 4000000               // E + E2 + NNZ
#define SCAN_BLK 1024
#define NB ((NT + SCAN_BLK - 1) / SCAN_BLK)
#define CHUNK 1000                   // divides NE and NE+NN exactly
#define NCHUNK (NT / CHUNK)

// -------- persistent scratch (static device globals) --------
__device__ __align__(16) __half g_all0[(size_t)NN * C];  // ping (fp16)
__device__ __align__(16) __half g_all1[(size_t)NN * C];  // pong (fp16)
__device__ __align__(16) __half g_wh[32 * C];            // combined weight tables (fp16)
__device__ __align__(16) float  g_f[2 * NE];             // ||sum||/cnt, double-buffered
__device__ int   g_cnt[NT];
__device__ int   g_rowptr[NT + 1];
__device__ int   g_cursor[NT];
__device__ int   g_perm[NT];                             // chunk-local degree-sorted map
__device__ unsigned long long g_scan_state[NB];          // (val<<2)|status for lookback
__device__ int   g_reci[MAXREC];                         // packed edge recs (head region)
__device__ __align__(16) int2 g_rec2[1000000];           // im recs {col, valbits} (CSR tail)

// buffer written by gather hop h (h = -1 means the initial embedding buffer)
__device__ __forceinline__ const __half* buf_of(int h) {
    return (h & 1) ? g_all0 : g_all1;
}
__device__ __forceinline__ __half* buf_of_mut(int h) {
    return (h & 1) ? g_all0 : g_all1;
}

// ---------------------------------------------------------------------------
// zero g_cnt + scan state
// ---------------------------------------------------------------------------
__global__ void zero_cnt_kernel() {
    int i = blockIdx.x * blockDim.x + threadIdx.x;
    if (i < NT / 4) ((int4*)g_cnt)[i] = make_int4(0, 0, 0, 0);
    if (i < NB) g_scan_state[i] = 0ULL;
}

// ---------------------------------------------------------------------------
// merged init + hist
// ---------------------------------------------------------------------------
__global__ void init_hist_kernel(const float* __restrict__ user_emb,
                                 const float* __restrict__ entity_emb,
                                 const float* __restrict__ w,
                                 const float* __restrict__ w2,
                                 const int* __restrict__ ei,
                                 const int* __restrict__ e2i,
                                 const int* __restrict__ im_row,
                                 int E, int E2, int NNZ) {
    const size_t rec_n = (size_t)E + E2 + NNZ;
    const size_t nn4   = (size_t)NN * C / 4;
    const size_t nu4   = (size_t)NU * C / 4;
    const size_t total = rec_n + nn4 + 31 * C;
    uint2*        all2 = (uint2*)g_all0;
    const float4* ue4  = (const float4*)user_emb;
    const float4* ee4  = (const float4*)entity_emb;
    for (size_t i = (size_t)blockIdx.x * blockDim.x + threadIdx.x;
         i < total; i += (size_t)gridDim.x * blockDim.x) {
        if (i < rec_n) {
            int d;
            if (i < (size_t)E)            d = ei[i];
            else if (i < (size_t)E + E2)  d = NE + e2i[i - E];
            else                          d = NE + NN + im_row[i - E - E2];
            atomicAdd(g_cnt + d, 1);
        } else if (i < rec_n + nn4) {
            size_t j = i - rec_n;
            float4 v = (j < nu4) ? ue4[j] : ee4[j - nu4];
            uint2 h;
            *(__half2*)&h.x = __floats2half2_rn(v.x, v.y);
            *(__half2*)&h.y = __floats2half2_rn(v.z, v.w);
            all2[j] = h;
        } else {
            size_t j = i - rec_n - nn4;
            float x = (j < 15 * C) ? w[j] : w2[j - 15 * C];
            g_wh[j] = __float2half_rn(x);
        }
    }
}

// ---------------------------------------------------------------------------
// single-kernel decoupled-lookback scan: g_cnt -> g_rowptr (+cursor)
// ---------------------------------------------------------------------------
__global__ void scan_lb_kernel(int total_rec) {
    __shared__ int s[256];
    __shared__ int s_prefix;
    int tid  = threadIdx.x;
    int b    = blockIdx.x;
    int base = b * SCAN_BLK + tid * 4;
    int v[4], t = 0;
    #pragma unroll
    for (int k = 0; k < 4; k++) {
        v[k] = (base + k < NT) ? g_cnt[base + k] : 0;
        t += v[k];
    }
    s[tid] = t;
    __syncthreads();
    #pragma unroll
    for (int off = 1; off < 256; off <<= 1) {
        int x = (tid >= off) ? s[tid - off] : 0;
        __syncthreads();
        s[tid] += x;
        __syncthreads();
    }
    int incl_local = s[tid];
    if (tid == 0) {
        int block_total = s[255];
        atomicExch(&g_scan_state[b],
                   ((unsigned long long)(unsigned)block_total << 2) | 1ULL);
        int prefix = 0;
        for (int j = b - 1; j >= 0; j--) {
            unsigned long long st;
            do { st = atomicAdd(&g_scan_state[j], 0ULL); } while ((st & 3ULL) == 0ULL);
            prefix += (int)(unsigned)(st >> 2);
            if ((st & 3ULL) == 2ULL) break;
        }
        atomicExch(&g_scan_state[b],
                   ((unsigned long long)(unsigned)(prefix + block_total) << 2) | 2ULL);
        s_prefix = prefix;
        if (b == 0) g_rowptr[NT] = total_rec;
    }
    __syncthreads();
    int run = s_prefix + incl_local - t;    // global exclusive prefix
    #pragma unroll
    for (int k = 0; k < 4; k++) {
        if (base + k < NT) { g_rowptr[base + k] = run; g_cursor[base + k] = run; }
        run += v[k];
    }
}

// ---------------------------------------------------------------------------
// chunk-local degree sort: counting sort of rows by degree inside each
// CHUNK-row window (locality preserved; warps see equal-degree rows)
// ---------------------------------------------------------------------------
__global__ void chunk_sort_kernel() {
    __shared__ int hist[64];
    __shared__ int rowdeg[CHUNK];
    int base = blockIdx.x * CHUNK;
    int tid  = threadIdx.x;
    if (tid < 64) hist[tid] = 0;
    __syncthreads();
    for (int k = tid; k < CHUNK; k += blockDim.x) {
        int r = base + k;
        int d = min(g_rowptr[r + 1] - g_rowptr[r], 63);
        rowdeg[k] = d;
        atomicAdd(&hist[d], 1);
    }
    __syncthreads();
    if (tid == 0) {
        int run = 0;
        #pragma unroll
        for (int b = 0; b < 64; b++) { int x = hist[b]; hist[b] = run; run += x; }
    }
    __syncthreads();
    for (int k = tid; k < CHUNK; k += blockDim.x) {
        int pos = atomicAdd(&hist[rowdeg[k]], 1);
        g_perm[base + pos] = base + k;
    }
}

// ---------------------------------------------------------------------------
// fill: 4 records per thread. Edge recs -> one 4B write;
// im recs -> one 8B int2 write (col, valbits) in the CSR tail.
// ---------------------------------------------------------------------------
__global__ void __launch_bounds__(256) fill_kernel(
    const int* __restrict__ ei,  const int* __restrict__ ety,
    const int* __restrict__ e2i, const int* __restrict__ e2ty,
    const int* __restrict__ im_row, const int* __restrict__ im_col,
    const float* __restrict__ im_val,
    int E, int E2, int NNZ)
{
    int total = E + E2 + NNZ;
    int EE2   = E + E2;
    int base  = (blockIdx.x * blockDim.x + threadIdx.x) * 4;
    if (base >= total) return;

    int  d[4], ival[4], ival2[4];
    bool valid[4], is_im[4];
    #pragma unroll
    for (int k = 0; k < 4; k++) {
        int i = base + k;
        valid[k] = (i < total);
        d[k] = 0; ival[k] = 0; ival2[k] = 0; is_im[k] = false;
        if (!valid[k]) continue;
        if (i < E) {
            d[k]    = ei[i];
            ival[k] = (NU + ei[E + i]) * 32 + (ety[i] - 1);
        } else if (i < EE2) {
            int e2  = i - E;
            d[k]    = NE + e2i[e2];
            ival[k] = e2i[E2 + e2] * 32 + (15 + e2ty[e2]);
        } else {
            int j    = i - EE2;
            d[k]     = NE + NN + im_row[j];
            ival[k]  = im_col[j];
            ival2[k] = __float_as_int(im_val[j]);
            is_im[k] = true;
        }
    }
    int pos[4];
    #pragma unroll
    for (int k = 0; k < 4; k++)
        if (valid[k]) pos[k] = atomicAdd(g_cursor + d[k], 1);
    #pragma unroll
    for (int k = 0; k < 4; k++) {
        if (!valid[k]) continue;
        if (is_im[k]) g_rec2[pos[k] - EE2] = make_int2(ival[k], ival2[k]);
        else          g_reci[pos[k]]       = ival[k];
    }
}

// ---------------------------------------------------------------------------
// fused per-hop kernel: 8-lane group per destination row, chunk-local
// degree-sorted slot -> row mapping via g_perm.
// ---------------------------------------------------------------------------
__device__ __forceinline__ float grp_sum8(float s) {
    #pragma unroll
    for (int o = 4; o; o >>= 1) s += __shfl_xor_sync(0xffffffffu, s, o);
    return s;
}

struct F8 { float4 a, b; };

__device__ __forceinline__ F8 h8_to_f8(uint4 h) {
    F8 r;
    float2 p0 = __half22float2(*(__half2*)&h.x);
    float2 p1 = __half22float2(*(__half2*)&h.y);
    float2 p2 = __half22float2(*(__half2*)&h.z);
    float2 p3 = __half22float2(*(__half2*)&h.w);
    r.a = make_float4(p0.x, p0.y, p1.x, p1.y);
    r.b = make_float4(p2.x, p2.y, p3.x, p3.y);
    return r;
}

__global__ void __launch_bounds__(256) fused_kernel(
    int hop_g, int do_g, int hop_m, int do_m, int base, int EE2,
    const float* __restrict__ user_emb, const float* __restrict__ entity_emb,
    float* __restrict__ node_res, float* __restrict__ ent_out,
    float* __restrict__ user_res)
{
    int gslot = base + ((blockIdx.x * blockDim.x + threadIdx.x) >> 3);
    if (gslot >= NT) return;
    int gidx = __ldg(g_perm + gslot);     // chunk-local shuffle: region-preserving
    int lane = threadIdx.x & 7;

    if (gidx < NE + NN) {
        // ---------------- gather path (hop_g) ----------------
        if (!do_g) return;
        const __half* prev = buf_of(hop_g - 1);
        __half*       next = buf_of_mut(hop_g);
        float*        fdst = g_f + (hop_g & 1) * NE;
        int hop0 = (hop_g == 0);

        int start = g_rowptr[gidx], end = g_rowptr[gidx + 1];
        float4 accA = make_float4(0.f, 0.f, 0.f, 0.f);
        float4 accB = make_float4(0.f, 0.f, 0.f, 0.f);
        int e = start;
        for (; e + 1 < end; e += 2) {
            int r0 = __ldg(g_reci + e);
            int r1 = __ldg(g_reci + e + 1);
            uint4 h0 = *((const uint4*)(prev + (size_t)(r0 >> 5) * C) + lane);
            uint4 h1 = *((const uint4*)(prev + (size_t)(r1 >> 5) * C) + lane);
            uint4 wh0 = *((const uint4*)(g_wh + (r0 & 31) * C) + lane);
            uint4 wh1 = *((const uint4*)(g_wh + (r1 & 31) * C) + lane);
            F8 s0 = h8_to_f8(h0), s1 = h8_to_f8(h1);
            F8 w0 = h8_to_f8(wh0), w1 = h8_to_f8(wh1);
            accA.x += s0.a.x * w0.a.x + s1.a.x * w1.a.x;
            accA.y += s0.a.y * w0.a.y + s1.a.y * w1.a.y;
            accA.z += s0.a.z * w0.a.z + s1.a.z * w1.a.z;
            accA.w += s0.a.w * w0.a.w + s1.a.w * w1.a.w;
            accB.x += s0.b.x * w0.b.x + s1.b.x * w1.b.x;
            accB.y += s0.b.y * w0.b.y + s1.b.y * w1.b.y;
            accB.z += s0.b.z * w0.b.z + s1.b.z * w1.b.z;
            accB.w += s0.b.w * w0.b.w + s1.b.w * w1.b.w;
        }
        if (e < end) {
            int r0 = __ldg(g_reci + e);
            uint4 h0 = *((const uint4*)(prev + (size_t)(r0 >> 5) * C) + lane);
            uint4 wh0 = *((const uint4*)(g_wh + (r0 & 31) * C) + lane);
            F8 s0 = h8_to_f8(h0);
            F8 w0 = h8_to_f8(wh0);
            accA.x += s0.a.x * w0.a.x; accA.y += s0.a.y * w0.a.y;
            accA.z += s0.a.z * w0.a.z; accA.w += s0.a.w * w0.a.w;
            accB.x += s0.b.x * w0.b.x; accB.y += s0.b.y * w0.b.y;
            accB.z += s0.b.z * w0.b.z; accB.w += s0.b.w * w0.b.w;
        }

        float ss = grp_sum8(accA.x * accA.x + accA.y * accA.y + accA.z * accA.z + accA.w * accA.w
                          + accB.x * accB.x + accB.y * accB.y + accB.z * accB.z + accB.w * accB.w);
        float n  = sqrtf(ss);
        float inv = 1.0f / fmaxf(n, 1e-12f);
        float4 oa = make_float4(accA.x * inv, accA.y * inv, accA.z * inv, accA.w * inv);
        float4 ob = make_float4(accB.x * inv, accB.y * inv, accB.z * inv, accB.w * inv);
        uint4 oh;
        *(__half2*)&oh.x = __floats2half2_rn(oa.x, oa.y);
        *(__half2*)&oh.y = __floats2half2_rn(oa.z, oa.w);
        *(__half2*)&oh.z = __floats2half2_rn(ob.x, ob.y);
        *(__half2*)&oh.w = __floats2half2_rn(ob.z, ob.w);

        if (gidx < NE) {
            *((uint4*)(next + (size_t)(NU + gidx) * C) + lane) = oh;
            if (lane == 0) fdst[gidx] = n / fmaxf((float)(end - start), 1.0f);
            if (hop_g == N_HOPS - 1) {
                float4* op = (float4*)(ent_out + (size_t)gidx * C) + lane * 2;
                op[0] = oa; op[1] = ob;
            }
        } else {
            int r = gidx - NE;
            // user-half of the state buffer is dead after the last hop
            if (r < NU && hop_g != N_HOPS - 1)
                *((uint4*)(next + (size_t)r * C) + lane) = oh;
            float4* rp = (float4*)(node_res + (size_t)r * C) + lane * 2;
            float4 a0, a1;
            if (hop0) {
                const float4* ip = (r < NU)
                    ? (const float4*)(user_emb + (size_t)r * C) + lane * 2
                    : (const float4*)(entity_emb + (size_t)(r - NU) * C) + lane * 2;
                a0 = ip[0]; a1 = ip[1];
            } else {
                a0 = rp[0]; a1 = rp[1];
            }
            a0.x += oa.x; a0.y += oa.y; a0.z += oa.z; a0.w += oa.w;
            a1.x += ob.x; a1.y += ob.y; a1.z += ob.z; a1.w += ob.w;
            rp[0] = a0; rp[1] = a1;
        }
    } else {
        // ---------------- im path (hop_m) ----------------
        if (!do_m) return;
        const __half* src  = buf_of(hop_m);
        const float*  fsrc = g_f + (hop_m & 1) * NE;
        int hop0 = (hop_m == 0);
        int u = gidx - NE - NN;

        int start = g_rowptr[gidx], end = g_rowptr[gidx + 1];
        float4 accA = make_float4(0.f, 0.f, 0.f, 0.f);
        float4 accB = make_float4(0.f, 0.f, 0.f, 0.f);
        int e = start;
        for (; e + 1 < end; e += 2) {
            int2 r0 = __ldg(g_rec2 + (e - EE2));
            int2 r1 = __ldg(g_rec2 + (e + 1 - EE2));
            float c0 = __int_as_float(r0.y) * __ldg(fsrc + r0.x);
            float c1 = __int_as_float(r1.y) * __ldg(fsrc + r1.x);
            uint4 h0 = *((const uint4*)(src + (size_t)(NU + r0.x) * C) + lane);
            uint4 h1 = *((const uint4*)(src + (size_t)(NU + r1.x) * C) + lane);
            F8 s0 = h8_to_f8(h0);
            F8 s1 = h8_to_f8(h1);
            accA.x += s0.a.x * c0 + s1.a.x * c1;
            accA.y += s0.a.y * c0 + s1.a.y * c1;
            accA.z += s0.a.z * c0 + s1.a.z * c1;
            accA.w += s0.a.w * c0 + s1.a.w * c1;
            accB.x += s0.b.x * c0 + s1.b.x * c1;
            accB.y += s0.b.y * c0 + s1.b.y * c1;
            accB.z += s0.b.z * c0 + s1.b.z * c1;
            accB.w += s0.b.w * c0 + s1.b.w * c1;
        }
        if (e < end) {
            int2 r0 = __ldg(g_rec2 + (e - EE2));
            float c0 = __int_as_float(r0.y) * __ldg(fsrc + r0.x);
            uint4 h0 = *((const uint4*)(src + (size_t)(NU + r0.x) * C) + lane);
            F8 s0 = h8_to_f8(h0);
            accA.x += s0.a.x * c0; accA.y += s0.a.y * c0;
            accA.z += s0.a.z * c0; accA.w += s0.a.w * c0;
            accB.x += s0.b.x * c0; accB.y += s0.b.y * c0;
            accB.z += s0.b.z * c0; accB.w += s0.b.w * c0;
        }

        float ss = grp_sum8(accA.x * accA.x + accA.y * accA.y + accA.z * accA.z + accA.w * accA.w
                          + accB.x * accB.x + accB.y * accB.y + accB.z * accB.z + accB.w * accB.w);
        float inv = 1.0f / fmaxf(sqrtf(ss), 1e-12f);
        float4* rp = (float4*)(user_res + (size_t)u * C) + lane * 2;
        float4 a0, a1;
        if (hop0) {
            const float4* ip = (const float4*)(user_emb + (size_t)u * C) + lane * 2;
            a0 = ip[0]; a1 = ip[1];
        } else {
            a0 = rp[0]; a1 = rp[1];
        }
        a0.x += accA.x * inv; a0.y += accA.y * inv;
        a0.z += accA.z * inv; a0.w += accA.w * inv;
        a1.x += accB.x * inv; a1.y += accB.y * inv;
        a1.z += accB.z * inv; a1.w += accB.w * inv;
        rp[0] = a0; rp[1] = a1;
    }
}

// ---------------------------------------------------------------------------
extern "C" void kernel_launch(void* const* d_in, const int* in_sizes, int n_in,
                              void* d_out, int out_size) {
    const float* user_emb     = (const float*)d_in[0];
    const float* entity_emb   = (const float*)d_in[1];
    const float* weight       = (const float*)d_in[2];
    const float* extra_weight = (const float*)d_in[3];
    const float* im_val       = (const float*)d_in[4];
    const int*   edge_index   = (const int*)d_in[5];
    const int*   edge_type    = (const int*)d_in[6];
    const int*   extra_eidx   = (const int*)d_in[7];
    const int*   extra_etype  = (const int*)d_in[8];
    const int*   im_row       = (const int*)d_in[9];
    const int*   im_col       = (const int*)d_in[10];

    const int E   = in_sizes[6];
    const int E2  = in_sizes[8];
    const int NNZ = in_sizes[4];
    const int total_rec = E + E2 + NNZ;
    const int EE2 = E + E2;

    float* out      = (float*)d_out;
    float* user_res = out;                      // [NU, C]
    float* ent_out  = out + (size_t)NU * C;     // [NE, C]
    float* node_res = out + (size_t)NN * C;     // [NN, C]

    zero_cnt_kernel<<<(NT / 4 + 255) / 256, 256>>>();
    init_hist_kernel<<<2048, 256>>>(user_emb, entity_emb, weight, extra_weight,
                                    edge_index, extra_eidx, im_row, E, E2, NNZ);
    scan_lb_kernel<<<NB, 256>>>(total_rec);
    chunk_sort_kernel<<<NCHUNK, 256>>>();
    fill_kernel<<<(total_rec + 1023) / 1024, 256>>>(edge_index, edge_type,
                                                    extra_eidx, extra_etype,
                                                    im_row, im_col, im_val, E, E2, NNZ);

    const int g_blocks  = ((NE + NN) * 8 + 255) / 256;   // gather-only
    const int gm_blocks = (NT * 8 + 255) / 256;          // gather + im
    const int m_blocks  = (NU * 8 + 255) / 256;          // im-only

    // g0 ; [im0 || g1] ; [im1 || g2] ; im2
    fused_kernel<<<g_blocks, 256>>>(0, 1, 0, 0, 0, EE2,
                                    user_emb, entity_emb, node_res, ent_out, user_res);
    fused_kernel<<<gm_blocks, 256>>>(1, 1, 0, 1, 0, EE2,
                                     user_emb, entity_emb, node_res, ent_out, user_res);
    fused_kernel<<<gm_blocks, 256>>>(2, 1, 1, 1, 0, EE2,
                                     user_emb, entity_emb, node_res, ent_out, user_res);
    fused_kernel<<<m_blocks, 256>>>(0, 0, 2, 1, NE + NN, EE2,
                                    user_emb, entity_emb, node_res, ent_out, user_res);
}

// round 16
// speedup vs baseline: 1.0855x; 1.0311x over previous
#include <cuda_runtime.h>
#include <cuda_fp16.h>

#define NU 100000
#define NE 100000
#define NN 200000
#define C  64
#define N_HOPS 3
#define NT (NE + NN + NU)            // combined destination space
#define MAXREC 4000000               // E + E2 + NNZ
#define SCAN_BLK 1024
#define NB ((NT + SCAN_BLK - 1) / SCAN_BLK)
#define CHUNK 1000                   // divides NE and NE+NN exactly
#define NCHUNK (NT / CHUNK)

// -------- persistent scratch (static device globals) --------
__device__ __align__(16) __half g_all0[(size_t)NN * C];  // ping (fp16)
__device__ __align__(16) __half g_all1[(size_t)NN * C];  // pong (fp16)
__device__ __align__(16) __half g_wh[32 * C];            // combined weight tables (fp16)
__device__ __align__(16) float  g_f[2 * NE];             // ||sum||/cnt, double-buffered
__device__ int   g_cnt[NT];
__device__ int   g_rowptr[NT + 1];                       // indexed by SLOT (post-perm)
__device__ int   g_perm[NT];                             // slot -> row
__device__ int   g_iperm[NT];                            // row -> slot
__device__ int   g_seq[MAXREC];                          // per-record seq within its row
__device__ unsigned long long g_scan_state[NB];          // (val<<2)|status for lookback
__device__ int   g_reci[MAXREC];                         // packed edge recs (slot-ordered)
__device__ __align__(16) int2 g_rec2[1000000];           // im recs {col, valbits} (CSR tail)

// buffer written by gather hop h (h = -1 means the initial embedding buffer)
__device__ __forceinline__ const __half* buf_of(int h) {
    return (h & 1) ? g_all0 : g_all1;
}
__device__ __forceinline__ __half* buf_of_mut(int h) {
    return (h & 1) ? g_all0 : g_all1;
}

// ---------------------------------------------------------------------------
// zero g_cnt + scan state
// ---------------------------------------------------------------------------
__global__ void zero_cnt_kernel() {
    int i = blockIdx.x * blockDim.x + threadIdx.x;
    if (i < NT / 4) ((int4*)g_cnt)[i] = make_int4(0, 0, 0, 0);
    if (i < NB) g_scan_state[i] = 0ULL;
}

// ---------------------------------------------------------------------------
// merged init + hist; records per-record sequence number (atomic return)
// ---------------------------------------------------------------------------
__global__ void init_hist_kernel(const float* __restrict__ user_emb,
                                 const float* __restrict__ entity_emb,
                                 const float* __restrict__ w,
                                 const float* __restrict__ w2,
                                 const int* __restrict__ ei,
                                 const int* __restrict__ e2i,
                                 const int* __restrict__ im_row,
                                 int E, int E2, int NNZ) {
    const size_t rec_n = (size_t)E + E2 + NNZ;
    const size_t nn4   = (size_t)NN * C / 4;
    const size_t nu4   = (size_t)NU * C / 4;
    const size_t total = rec_n + nn4 + 31 * C;
    uint2*        all2 = (uint2*)g_all0;
    const float4* ue4  = (const float4*)user_emb;
    const float4* ee4  = (const float4*)entity_emb;
    for (size_t i = (size_t)blockIdx.x * blockDim.x + threadIdx.x;
         i < total; i += (size_t)gridDim.x * blockDim.x) {
        if (i < rec_n) {
            int d;
            if (i < (size_t)E)            d = ei[i];
            else if (i < (size_t)E + E2)  d = NE + e2i[i - E];
            else                          d = NE + NN + im_row[i - E - E2];
            g_seq[i] = atomicAdd(g_cnt + d, 1);
        } else if (i < rec_n + nn4) {
            size_t j = i - rec_n;
            float4 v = (j < nu4) ? ue4[j] : ee4[j - nu4];
            uint2 h;
            *(__half2*)&h.x = __floats2half2_rn(v.x, v.y);
            *(__half2*)&h.y = __floats2half2_rn(v.z, v.w);
            all2[j] = h;
        } else {
            size_t j = i - rec_n - nn4;
            float x = (j < 15 * C) ? w[j] : w2[j - 15 * C];
            g_wh[j] = __float2half_rn(x);
        }
    }
}

// ---------------------------------------------------------------------------
// chunk-local degree sort (degrees from g_cnt): perm + inverse perm
// ---------------------------------------------------------------------------
__global__ void chunk_sort_kernel() {
    __shared__ int hist[64];
    __shared__ int rowdeg[CHUNK];
    int base = blockIdx.x * CHUNK;
    int tid  = threadIdx.x;
    if (tid < 64) hist[tid] = 0;
    __syncthreads();
    for (int k = tid; k < CHUNK; k += blockDim.x) {
        int d = min(g_cnt[base + k], 63);
        rowdeg[k] = d;
        atomicAdd(&hist[d], 1);
    }
    __syncthreads();
    if (tid == 0) {
        int run = 0;
        #pragma unroll
        for (int b = 0; b < 64; b++) { int x = hist[b]; hist[b] = run; run += x; }
    }
    __syncthreads();
    for (int k = tid; k < CHUNK; k += blockDim.x) {
        int pos = atomicAdd(&hist[rowdeg[k]], 1);
        g_perm[base + pos]  = base + k;
        g_iperm[base + k]   = base + pos;
    }
}

// ---------------------------------------------------------------------------
// lookback scan over SLOT order: rowptr[slot] = prefix of cnt[perm[slot]]
// ---------------------------------------------------------------------------
__global__ void scan_lb_kernel(int total_rec) {
    __shared__ int s[256];
    __shared__ int s_prefix;
    int tid  = threadIdx.x;
    int b    = blockIdx.x;
    int base = b * SCAN_BLK + tid * 4;
    int v[4], t = 0;
    #pragma unroll
    for (int k = 0; k < 4; k++) {
        v[k] = (base + k < NT) ? g_cnt[g_perm[base + k]] : 0;
        t += v[k];
    }
    s[tid] = t;
    __syncthreads();
    #pragma unroll
    for (int off = 1; off < 256; off <<= 1) {
        int x = (tid >= off) ? s[tid - off] : 0;
        __syncthreads();
        s[tid] += x;
        __syncthreads();
    }
    int incl_local = s[tid];
    if (tid == 0) {
        int block_total = s[255];
        atomicExch(&g_scan_state[b],
                   ((unsigned long long)(unsigned)block_total << 2) | 1ULL);
        int prefix = 0;
        for (int j = b - 1; j >= 0; j--) {
            unsigned long long st;
            do { st = atomicAdd(&g_scan_state[j], 0ULL); } while ((st & 3ULL) == 0ULL);
            prefix += (int)(unsigned)(st >> 2);
            if ((st & 3ULL) == 2ULL) break;
        }
        atomicExch(&g_scan_state[b],
                   ((unsigned long long)(unsigned)(prefix + block_total) << 2) | 2ULL);
        s_prefix = prefix;
        if (b == 0) g_rowptr[NT] = total_rec;
    }
    __syncthreads();
    int run = s_prefix + incl_local - t;    // global exclusive prefix (slot order)
    #pragma unroll
    for (int k = 0; k < 4; k++) {
        if (base + k < NT) g_rowptr[base + k] = run;
        run += v[k];
    }
}

// ---------------------------------------------------------------------------
// fill (atomic-free): pos = rowptr[iperm[row]] + seq[i]
// 4 records per thread; edge recs 4B, im recs 8B int2 in the CSR tail
// ---------------------------------------------------------------------------
__global__ void __launch_bounds__(256) fill_kernel(
    const int* __restrict__ ei,  const int* __restrict__ ety,
    const int* __restrict__ e2i, const int* __restrict__ e2ty,
    const int* __restrict__ im_row, const int* __restrict__ im_col,
    const float* __restrict__ im_val,
    int E, int E2, int NNZ)
{
    int total = E + E2 + NNZ;
    int EE2   = E + E2;
    int base  = (blockIdx.x * blockDim.x + threadIdx.x) * 4;
    if (base >= total) return;

    int  d[4], ival[4], ival2[4];
    bool valid[4], is_im[4];
    #pragma unroll
    for (int k = 0; k < 4; k++) {
        int i = base + k;
        valid[k] = (i < total);
        d[k] = 0; ival[k] = 0; ival2[k] = 0; is_im[k] = false;
        if (!valid[k]) continue;
        if (i < E) {
            d[k]    = ei[i];
            ival[k] = (NU + ei[E + i]) * 32 + (ety[i] - 1);
        } else if (i < EE2) {
            int e2  = i - E;
            d[k]    = NE + e2i[e2];
            ival[k] = e2i[E2 + e2] * 32 + (15 + e2ty[e2]);
        } else {
            int j    = i - EE2;
            d[k]     = NE + NN + im_row[j];
            ival[k]  = im_col[j];
            ival2[k] = __float_as_int(im_val[j]);
            is_im[k] = true;
        }
    }
    int pos[4];
    #pragma unroll
    for (int k = 0; k < 4; k++)
        if (valid[k]) pos[k] = __ldg(g_rowptr + __ldg(g_iperm + d[k])) + __ldg(g_seq + base + k);
    #pragma unroll
    for (int k = 0; k < 4; k++) {
        if (!valid[k]) continue;
        if (is_im[k]) g_rec2[pos[k] - EE2] = make_int2(ival[k], ival2[k]);
        else          g_reci[pos[k]]       = ival[k];
    }
}

// ---------------------------------------------------------------------------
// fused per-hop kernel: 8-lane group per slot; rowptr indexed by slot
// (contiguous), destination row via perm.
// ---------------------------------------------------------------------------
__device__ __forceinline__ float grp_sum8(float s) {
    #pragma unroll
    for (int o = 4; o; o >>= 1) s += __shfl_xor_sync(0xffffffffu, s, o);
    return s;
}

struct F8 { float4 a, b; };

__device__ __forceinline__ F8 h8_to_f8(uint4 h) {
    F8 r;
    float2 p0 = __half22float2(*(__half2*)&h.x);
    float2 p1 = __half22float2(*(__half2*)&h.y);
    float2 p2 = __half22float2(*(__half2*)&h.z);
    float2 p3 = __half22float2(*(__half2*)&h.w);
    r.a = make_float4(p0.x, p0.y, p1.x, p1.y);
    r.b = make_float4(p2.x, p2.y, p3.x, p3.y);
    return r;
}

__global__ void __launch_bounds__(256) fused_kernel(
    int hop_g, int do_g, int hop_m, int do_m, int base, int EE2,
    const float* __restrict__ user_emb, const float* __restrict__ entity_emb,
    float* __restrict__ node_res, float* __restrict__ ent_out,
    float* __restrict__ user_res)
{
    int gslot = base + ((blockIdx.x * blockDim.x + threadIdx.x) >> 3);
    if (gslot >= NT) return;
    int gidx = __ldg(g_perm + gslot);     // chunk-local shuffle: region-preserving
    int lane = threadIdx.x & 7;
    int start = __ldg(g_rowptr + gslot), end = __ldg(g_rowptr + gslot + 1);

    if (gidx < NE + NN) {
        // ---------------- gather path (hop_g) ----------------
        if (!do_g) return;
        const __half* prev = buf_of(hop_g - 1);
        __half*       next = buf_of_mut(hop_g);
        float*        fdst = g_f + (hop_g & 1) * NE;
        int hop0 = (hop_g == 0);

        float4 accA = make_float4(0.f, 0.f, 0.f, 0.f);
        float4 accB = make_float4(0.f, 0.f, 0.f, 0.f);
        int e = start;
        for (; e + 1 < end; e += 2) {
            int r0 = __ldg(g_reci + e);
            int r1 = __ldg(g_reci + e + 1);
            uint4 h0 = *((const uint4*)(prev + (size_t)(r0 >> 5) * C) + lane);
            uint4 h1 = *((const uint4*)(prev + (size_t)(r1 >> 5) * C) + lane);
            uint4 wh0 = *((const uint4*)(g_wh + (r0 & 31) * C) + lane);
            uint4 wh1 = *((const uint4*)(g_wh + (r1 & 31) * C) + lane);
            F8 s0 = h8_to_f8(h0), s1 = h8_to_f8(h1);
            F8 w0 = h8_to_f8(wh0), w1 = h8_to_f8(wh1);
            accA.x += s0.a.x * w0.a.x + s1.a.x * w1.a.x;
            accA.y += s0.a.y * w0.a.y + s1.a.y * w1.a.y;
            accA.z += s0.a.z * w0.a.z + s1.a.z * w1.a.z;
            accA.w += s0.a.w * w0.a.w + s1.a.w * w1.a.w;
            accB.x += s0.b.x * w0.b.x + s1.b.x * w1.b.x;
            accB.y += s0.b.y * w0.b.y + s1.b.y * w1.b.y;
            accB.z += s0.b.z * w0.b.z + s1.b.z * w1.b.z;
            accB.w += s0.b.w * w0.b.w + s1.b.w * w1.b.w;
        }
        if (e < end) {
            int r0 = __ldg(g_reci + e);
            uint4 h0 = *((const uint4*)(prev + (size_t)(r0 >> 5) * C) + lane);
            uint4 wh0 = *((const uint4*)(g_wh + (r0 & 31) * C) + lane);
            F8 s0 = h8_to_f8(h0);
            F8 w0 = h8_to_f8(wh0);
            accA.x += s0.a.x * w0.a.x; accA.y += s0.a.y * w0.a.y;
            accA.z += s0.a.z * w0.a.z; accA.w += s0.a.w * w0.a.w;
            accB.x += s0.b.x * w0.b.x; accB.y += s0.b.y * w0.b.y;
            accB.z += s0.b.z * w0.b.z; accB.w += s0.b.w * w0.b.w;
        }

        float ss = grp_sum8(accA.x * accA.x + accA.y * accA.y + accA.z * accA.z + accA.w * accA.w
                          + accB.x * accB.x + accB.y * accB.y + accB.z * accB.z + accB.w * accB.w);
        float n  = sqrtf(ss);
        float inv = 1.0f / fmaxf(n, 1e-12f);
        float4 oa = make_float4(accA.x * inv, accA.y * inv, accA.z * inv, accA.w * inv);
        float4 ob = make_float4(accB.x * inv, accB.y * inv, accB.z * inv, accB.w * inv);
        uint4 oh;
        *(__half2*)&oh.x = __floats2half2_rn(oa.x, oa.y);
        *(__half2*)&oh.y = __floats2half2_rn(oa.z, oa.w);
        *(__half2*)&oh.z = __floats2half2_rn(ob.x, ob.y);
        *(__half2*)&oh.w = __floats2half2_rn(ob.z, ob.w);

        if (gidx < NE) {
            *((uint4*)(next + (size_t)(NU + gidx) * C) + lane) = oh;
            if (lane == 0) fdst[gidx] = n / fmaxf((float)(end - start), 1.0f);
            if (hop_g == N_HOPS - 1) {
                float4* op = (float4*)(ent_out + (size_t)gidx * C) + lane * 2;
                op[0] = oa; op[1] = ob;
            }
        } else {
            int r = gidx - NE;
            // user-half of the state buffer is dead after the last hop
            if (r < NU && hop_g != N_HOPS - 1)
                *((uint4*)(next + (size_t)r * C) + lane) = oh;
            float4* rp = (float4*)(node_res + (size_t)r * C) + lane * 2;
            float4 a0, a1;
            if (hop0) {
                const float4* ip = (r < NU)
                    ? (const float4*)(user_emb + (size_t)r * C) + lane * 2
                    : (const float4*)(entity_emb + (size_t)(r - NU) * C) + lane * 2;
                a0 = ip[0]; a1 = ip[1];
            } else {
                a0 = rp[0]; a1 = rp[1];
            }
            a0.x += oa.x; a0.y += oa.y; a0.z += oa.z; a0.w += oa.w;
            a1.x += ob.x; a1.y += ob.y; a1.z += ob.z; a1.w += ob.w;
            rp[0] = a0; rp[1] = a1;
        }
    } else {
        // ---------------- im path (hop_m) ----------------
        if (!do_m) return;
        const __half* src  = buf_of(hop_m);
        const float*  fsrc = g_f + (hop_m & 1) * NE;
        int hop0 = (hop_m == 0);
        int u = gidx - NE - NN;

        float4 accA = make_float4(0.f, 0.f, 0.f, 0.f);
        float4 accB = make_float4(0.f, 0.f, 0.f, 0.f);
        int e = start;
        for (; e + 1 < end; e += 2) {
            int2 r0 = __ldg(g_rec2 + (e - EE2));
            int2 r1 = __ldg(g_rec2 + (e + 1 - EE2));
            float c0 = __int_as_float(r0.y) * __ldg(fsrc + r0.x);
            float c1 = __int_as_float(r1.y) * __ldg(fsrc + r1.x);
            uint4 h0 = *((const uint4*)(src + (size_t)(NU + r0.x) * C) + lane);
            uint4 h1 = *((const uint4*)(src + (size_t)(NU + r1.x) * C) + lane);
            F8 s0 = h8_to_f8(h0);
            F8 s1 = h8_to_f8(h1);
            accA.x += s0.a.x * c0 + s1.a.x * c1;
            accA.y += s0.a.y * c0 + s1.a.y * c1;
            accA.z += s0.a.z * c0 + s1.a.z * c1;
            accA.w += s0.a.w * c0 + s1.a.w * c1;
            accB.x += s0.b.x * c0 + s1.b.x * c1;
            accB.y += s0.b.y * c0 + s1.b.y * c1;
            accB.z += s0.b.z * c0 + s1.b.z * c1;
            accB.w += s0.b.w * c0 + s1.b.w * c1;
        }
        if (e < end) {
            int2 r0 = __ldg(g_rec2 + (e - EE2));
            float c0 = __int_as_float(r0.y) * __ldg(fsrc + r0.x);
            uint4 h0 = *((const uint4*)(src + (size_t)(NU + r0.x) * C) + lane);
            F8 s0 = h8_to_f8(h0);
            accA.x += s0.a.x * c0; accA.y += s0.a.y * c0;
            accA.z += s0.a.z * c0; accA.w += s0.a.w * c0;
            accB.x += s0.b.x * c0; accB.y += s0.b.y * c0;
            accB.z += s0.b.z * c0; accB.w += s0.b.w * c0;
        }

        float ss = grp_sum8(accA.x * accA.x + accA.y * accA.y + accA.z * accA.z + accA.w * accA.w
                          + accB.x * accB.x + accB.y * accB.y + accB.z * accB.z + accB.w * accB.w);
        float inv = 1.0f / fmaxf(sqrtf(ss), 1e-12f);
        float4* rp = (float4*)(user_res + (size_t)u * C) + lane * 2;
        float4 a0, a1;
        if (hop0) {
            const float4* ip = (const float4*)(user_emb + (size_t)u * C) + lane * 2;
            a0 = ip[0]; a1 = ip[1];
        } else {
            a0 = rp[0]; a1 = rp[1];
        }
        a0.x += accA.x * inv; a0.y += accA.y * inv;
        a0.z += accA.z * inv; a0.w += accA.w * inv;
        a1.x += accB.x * inv; a1.y += accB.y * inv;
        a1.z += accB.z * inv; a1.w += accB.w * inv;
        rp[0] = a0; rp[1] = a1;
    }
}

// ---------------------------------------------------------------------------
extern "C" void kernel_launch(void* const* d_in, const int* in_sizes, int n_in,
                              void* d_out, int out_size) {
    const float* user_emb     = (const float*)d_in[0];
    const float* entity_emb   = (const float*)d_in[1];
    const float* weight       = (const float*)d_in[2];
    const float* extra_weight = (const float*)d_in[3];
    const float* im_val       = (const float*)d_in[4];
    const int*   edge_index   = (const int*)d_in[5];
    const int*   edge_type    = (const int*)d_in[6];
    const int*   extra_eidx   = (const int*)d_in[7];
    const int*   extra_etype  = (const int*)d_in[8];
    const int*   im_row       = (const int*)d_in[9];
    const int*   im_col       = (const int*)d_in[10];

    const int E   = in_sizes[6];
    const int E2  = in_sizes[8];
    const int NNZ = in_sizes[4];
    const int total_rec = E + E2 + NNZ;
    const int EE2 = E + E2;

    float* out      = (float*)d_out;
    float* user_res = out;                      // [NU, C]
    float* ent_out  = out + (size_t)NU * C;     // [NE, C]
    float* node_res = out + (size_t)NN * C;     // [NN, C]

    zero_cnt_kernel<<<(NT / 4 + 255) / 256, 256>>>();
    init_hist_kernel<<<2048, 256>>>(user_emb, entity_emb, weight, extra_weight,
                                    edge_index, extra_eidx, im_row, E, E2, NNZ);
    chunk_sort_kernel<<<NCHUNK, 256>>>();
    scan_lb_kernel<<<NB, 256>>>(total_rec);
    fill_kernel<<<(total_rec + 1023) / 1024, 256>>>(edge_index, edge_type,
                                                    extra_eidx, extra_etype,
                                                    im_row, im_col, im_val, E, E2, NNZ);

    const int g_blocks  = ((NE + NN) * 8 + 255) / 256;   // gather-only
    const int gm_blocks = (NT * 8 + 255) / 256;          // gather + im
    const int m_blocks  = (NU * 8 + 255) / 256;          // im-only

    // g0 ; [im0 || g1] ; [im1 || g2] ; im2
    fused_kernel<<<g_blocks, 256>>>(0, 1, 0, 0, 0, EE2,
                                    user_emb, entity_emb, node_res, ent_out, user_res);
    fused_kernel<<<gm_blocks, 256>>>(1, 1, 0, 1, 0, EE2,
                                     user_emb, entity_emb, node_res, ent_out, user_res);
    fused_kernel<<<gm_blocks, 256>>>(2, 1, 1, 1, 0, EE2,
                                     user_emb, entity_emb, node_res, ent_out, user_res);
    fused_kernel<<<m_blocks, 256>>>(0, 0, 2, 1, NE + NN, EE2,
                                    user_emb, entity_emb, node_res, ent_out, user_res);
}

// round 17
// speedup vs baseline: 1.1095x; 1.0222x over previous
#include <cuda_runtime.h>
#include <cuda_fp16.h>

#define NU 100000
#define NE 100000
#define NN 200000
#define C  64
#define N_HOPS 3
#define NT (NE + NN + NU)            // combined destination space
#define MAXREC 4000000               // E + E2 + NNZ
#define SCAN_BLK 1024
#define NB ((NT + SCAN_BLK - 1) / SCAN_BLK)
#define CHUNK 1000                   // divides NE and NE+NN exactly
#define NCHUNK (NT / CHUNK)

// -------- persistent scratch (static device globals) --------
__device__ __align__(16) __half g_all0[(size_t)NN * C];  // ping (fp16)
__device__ __align__(16) __half g_all1[(size_t)NN * C];  // pong (fp16)
__device__ __align__(16) __half g_wh[32 * C];            // combined weight tables (fp16)
__device__ __align__(16) float  g_f[2 * NE];             // ||sum||/cnt, double-buffered
__device__ int   g_cnt[NT];
__device__ int   g_rowptr[NT + 1];                       // indexed by SLOT (post-perm)
__device__ int   g_perm[NT];                             // slot -> row
__device__ int   g_iperm[NT];                            // row -> slot
__device__ int   g_seq[MAXREC];                          // per-record seq within its row
__device__ unsigned long long g_scan_state[NB];          // (val<<2)|status for lookback
__device__ int   g_reci[MAXREC];                         // packed edge recs (slot-ordered)
__device__ __align__(16) int2 g_rec2[1000000];           // im recs {col, valbits} (CSR tail)

// buffer written by gather hop h (h = -1 means the initial embedding buffer)
__device__ __forceinline__ const __half* buf_of(int h) {
    return (h & 1) ? g_all0 : g_all1;
}
__device__ __forceinline__ __half* buf_of_mut(int h) {
    return (h & 1) ? g_all0 : g_all1;
}

// ---------------------------------------------------------------------------
// zero g_cnt + scan state
// ---------------------------------------------------------------------------
__global__ void zero_cnt_kernel() {
    int i = blockIdx.x * blockDim.x + threadIdx.x;
    if (i < NT / 4) ((int4*)g_cnt)[i] = make_int4(0, 0, 0, 0);
    if (i < NB) g_scan_state[i] = 0ULL;
}

// ---------------------------------------------------------------------------
// merged init + hist; records per-record sequence number (atomic return)
// ---------------------------------------------------------------------------
__global__ void init_hist_kernel(const float* __restrict__ user_emb,
                                 const float* __restrict__ entity_emb,
                                 const float* __restrict__ w,
                                 const float* __restrict__ w2,
                                 const int* __restrict__ ei,
                                 const int* __restrict__ e2i,
                                 const int* __restrict__ im_row,
                                 int E, int E2, int NNZ) {
    const size_t rec_n = (size_t)E + E2 + NNZ;
    const size_t nn4   = (size_t)NN * C / 4;
    const size_t nu4   = (size_t)NU * C / 4;
    const size_t total = rec_n + nn4 + 31 * C;
    uint2*        all2 = (uint2*)g_all0;
    const float4* ue4  = (const float4*)user_emb;
    const float4* ee4  = (const float4*)entity_emb;
    for (size_t i = (size_t)blockIdx.x * blockDim.x + threadIdx.x;
         i < total; i += (size_t)gridDim.x * blockDim.x) {
        if (i < rec_n) {
            int d;
            if (i < (size_t)E)            d = ei[i];
            else if (i < (size_t)E + E2)  d = NE + e2i[i - E];
            else                          d = NE + NN + im_row[i - E - E2];
            g_seq[i] = atomicAdd(g_cnt + d, 1);
        } else if (i < rec_n + nn4) {
            size_t j = i - rec_n;
            float4 v = (j < nu4) ? ue4[j] : ee4[j - nu4];
            uint2 h;
            *(__half2*)&h.x = __floats2half2_rn(v.x, v.y);
            *(__half2*)&h.y = __floats2half2_rn(v.z, v.w);
            all2[j] = h;
        } else {
            size_t j = i - rec_n - nn4;
            float x = (j < 15 * C) ? w[j] : w2[j - 15 * C];
            g_wh[j] = __float2half_rn(x);
        }
    }
}

// ---------------------------------------------------------------------------
// chunk-local degree sort (degrees from g_cnt): perm + inverse perm
// ---------------------------------------------------------------------------
__global__ void chunk_sort_kernel() {
    __shared__ int hist[64];
    __shared__ int rowdeg[CHUNK];
    int base = blockIdx.x * CHUNK;
    int tid  = threadIdx.x;
    if (tid < 64) hist[tid] = 0;
    __syncthreads();
    for (int k = tid; k < CHUNK; k += blockDim.x) {
        int d = min(g_cnt[base + k], 63);
        rowdeg[k] = d;
        atomicAdd(&hist[d], 1);
    }
    __syncthreads();
    if (tid == 0) {
        int run = 0;
        #pragma unroll
        for (int b = 0; b < 64; b++) { int x = hist[b]; hist[b] = run; run += x; }
    }
    __syncthreads();
    for (int k = tid; k < CHUNK; k += blockDim.x) {
        int pos = atomicAdd(&hist[rowdeg[k]], 1);
        g_perm[base + pos]  = base + k;
        g_iperm[base + k]   = base + pos;
    }
}

// ---------------------------------------------------------------------------
// lookback scan over SLOT order with warp-parallel lookback
// ---------------------------------------------------------------------------
__global__ void scan_lb_kernel(int total_rec) {
    __shared__ int s[256];
    __shared__ int s_prefix;
    int tid  = threadIdx.x;
    int b    = blockIdx.x;
    int base = b * SCAN_BLK + tid * 4;
    int v[4], t = 0;
    #pragma unroll
    for (int k = 0; k < 4; k++) {
        v[k] = (base + k < NT) ? g_cnt[g_perm[base + k]] : 0;
        t += v[k];
    }
    s[tid] = t;
    __syncthreads();
    #pragma unroll
    for (int off = 1; off < 256; off <<= 1) {
        int x = (tid >= off) ? s[tid - off] : 0;
        __syncthreads();
        s[tid] += x;
        __syncthreads();
    }
    int incl_local = s[tid];
    __shared__ int s_block_total;
    if (tid == 0) {
        s_block_total = s[255];
        atomicExch(&g_scan_state[b],
                   ((unsigned long long)(unsigned)s[255] << 2) | 1ULL);
    }
    __syncthreads();

    // warp-parallel lookback (first warp)
    if (tid < 32) {
        int lane = tid;
        int prefix = 0;
        int j = b - 1;
        while (j >= 0) {
            int idx = j - lane;
            unsigned long long st = 0ULL;
            if (idx >= 0) {
                do { st = atomicAdd(&g_scan_state[idx], 0ULL); }
                while ((st & 3ULL) == 0ULL);
            }
            int      val  = (idx >= 0) ? (int)(unsigned)(st >> 2) : 0;
            unsigned stat = (idx >= 0) ? (unsigned)(st & 3ULL) : 1u;
            unsigned pmask = __ballot_sync(0xffffffffu, stat == 2u);
            if (pmask) {
                int plane = __ffs(pmask) - 1;       // nearest inclusive-prefix block
                int contrib = (lane <= plane) ? val : 0;
                #pragma unroll
                for (int o = 16; o; o >>= 1)
                    contrib += __shfl_xor_sync(0xffffffffu, contrib, o);
                prefix += contrib;
                break;
            } else {
                int contrib = val;
                #pragma unroll
                for (int o = 16; o; o >>= 1)
                    contrib += __shfl_xor_sync(0xffffffffu, contrib, o);
                prefix += contrib;
                j -= 32;
            }
        }
        if (lane == 0) {
            atomicExch(&g_scan_state[b],
                       ((unsigned long long)(unsigned)(prefix + s_block_total) << 2) | 2ULL);
            s_prefix = prefix;
            if (b == 0) g_rowptr[NT] = total_rec;
        }
    }
    __syncthreads();
    int run = s_prefix + incl_local - t;    // global exclusive prefix (slot order)
    #pragma unroll
    for (int k = 0; k < 4; k++) {
        if (base + k < NT) g_rowptr[base + k] = run;
        run += v[k];
    }
}

// ---------------------------------------------------------------------------
// fill (atomic-free): pos = rowptr[iperm[row]] + seq[i]
// ---------------------------------------------------------------------------
__global__ void __launch_bounds__(256) fill_kernel(
    const int* __restrict__ ei,  const int* __restrict__ ety,
    const int* __restrict__ e2i, const int* __restrict__ e2ty,
    const int* __restrict__ im_row, const int* __restrict__ im_col,
    const float* __restrict__ im_val,
    int E, int E2, int NNZ)
{
    int total = E + E2 + NNZ;
    int EE2   = E + E2;
    int base  = (blockIdx.x * blockDim.x + threadIdx.x) * 4;
    if (base >= total) return;

    int  d[4], ival[4], ival2[4];
    bool valid[4], is_im[4];
    #pragma unroll
    for (int k = 0; k < 4; k++) {
        int i = base + k;
        valid[k] = (i < total);
        d[k] = 0; ival[k] = 0; ival2[k] = 0; is_im[k] = false;
        if (!valid[k]) continue;
        if (i < E) {
            d[k]    = ei[i];
            ival[k] = (NU + ei[E + i]) * 32 + (ety[i] - 1);
        } else if (i < EE2) {
            int e2  = i - E;
            d[k]    = NE + e2i[e2];
            ival[k] = e2i[E2 + e2] * 32 + (15 + e2ty[e2]);
        } else {
            int j    = i - EE2;
            d[k]     = NE + NN + im_row[j];
            ival[k]  = im_col[j];
            ival2[k] = __float_as_int(im_val[j]);
            is_im[k] = true;
        }
    }
    int pos[4];
    #pragma unroll
    for (int k = 0; k < 4; k++)
        if (valid[k]) pos[k] = __ldg(g_rowptr + __ldg(g_iperm + d[k])) + __ldg(g_seq + base + k);
    #pragma unroll
    for (int k = 0; k < 4; k++) {
        if (!valid[k]) continue;
        if (is_im[k]) g_rec2[pos[k] - EE2] = make_int2(ival[k], ival2[k]);
        else          g_reci[pos[k]]       = ival[k];
    }
}

// ---------------------------------------------------------------------------
// fused per-hop kernel: 8-lane group per slot; rowptr indexed by slot
// ---------------------------------------------------------------------------
__device__ __forceinline__ float grp_sum8(float s) {
    #pragma unroll
    for (int o = 4; o; o >>= 1) s += __shfl_xor_sync(0xffffffffu, s, o);
    return s;
}

struct F8 { float4 a, b; };

__device__ __forceinline__ F8 h8_to_f8(uint4 h) {
    F8 r;
    float2 p0 = __half22float2(*(__half2*)&h.x);
    float2 p1 = __half22float2(*(__half2*)&h.y);
    float2 p2 = __half22float2(*(__half2*)&h.z);
    float2 p3 = __half22float2(*(__half2*)&h.w);
    r.a = make_float4(p0.x, p0.y, p1.x, p1.y);
    r.b = make_float4(p2.x, p2.y, p3.x, p3.y);
    return r;
}

__global__ void __launch_bounds__(256) fused_kernel(
    int hop_g, int do_g, int hop_m, int do_m, int base, int EE2,
    const float* __restrict__ user_emb, const float* __restrict__ entity_emb,
    float* __restrict__ node_res, float* __restrict__ ent_out,
    float* __restrict__ user_res)
{
    int gslot = base + ((blockIdx.x * blockDim.x + threadIdx.x) >> 3);
    if (gslot >= NT) return;
    int gidx = __ldg(g_perm + gslot);     // chunk-local shuffle: region-preserving
    int lane = threadIdx.x & 7;
    int start = __ldg(g_rowptr + gslot), end = __ldg(g_rowptr + gslot + 1);

    if (gidx < NE + NN) {
        // ---------------- gather path (hop_g) ----------------
        if (!do_g) return;
        const __half* prev = buf_of(hop_g - 1);
        __half*       next = buf_of_mut(hop_g);
        float*        fdst = g_f + (hop_g & 1) * NE;
        int hop0 = (hop_g == 0);

        float4 accA = make_float4(0.f, 0.f, 0.f, 0.f);
        float4 accB = make_float4(0.f, 0.f, 0.f, 0.f);
        int e = start;
        for (; e + 1 < end; e += 2) {
            int r0 = __ldg(g_reci + e);
            int r1 = __ldg(g_reci + e + 1);
            uint4 h0 = *((const uint4*)(prev + (size_t)(r0 >> 5) * C) + lane);
            uint4 h1 = *((const uint4*)(prev + (size_t)(r1 >> 5) * C) + lane);
            uint4 wh0 = *((const uint4*)(g_wh + (r0 & 31) * C) + lane);
            uint4 wh1 = *((const uint4*)(g_wh + (r1 & 31) * C) + lane);
            F8 s0 = h8_to_f8(h0), s1 = h8_to_f8(h1);
            F8 w0 = h8_to_f8(wh0), w1 = h8_to_f8(wh1);
            accA.x += s0.a.x * w0.a.x + s1.a.x * w1.a.x;
            accA.y += s0.a.y * w0.a.y + s1.a.y * w1.a.y;
            accA.z += s0.a.z * w0.a.z + s1.a.z * w1.a.z;
            accA.w += s0.a.w * w0.a.w + s1.a.w * w1.a.w;
            accB.x += s0.b.x * w0.b.x + s1.b.x * w1.b.x;
            accB.y += s0.b.y * w0.b.y + s1.b.y * w1.b.y;
            accB.z += s0.b.z * w0.b.z + s1.b.z * w1.b.z;
            accB.w += s0.b.w * w0.b.w + s1.b.w * w1.b.w;
        }
        if (e < end) {
            int r0 = __ldg(g_reci + e);
            uint4 h0 = *((const uint4*)(prev + (size_t)(r0 >> 5) * C) + lane);
            uint4 wh0 = *((const uint4*)(g_wh + (r0 & 31) * C) + lane);
            F8 s0 = h8_to_f8(h0);
            F8 w0 = h8_to_f8(wh0);
            accA.x += s0.a.x * w0.a.x; accA.y += s0.a.y * w0.a.y;
            accA.z += s0.a.z * w0.a.z; accA.w += s0.a.w * w0.a.w;
            accB.x += s0.b.x * w0.b.x; accB.y += s0.b.y * w0.b.y;
            accB.z += s0.b.z * w0.b.z; accB.w += s0.b.w * w0.b.w;
        }

        float ss = grp_sum8(accA.x * accA.x + accA.y * accA.y + accA.z * accA.z + accA.w * accA.w
                          + accB.x * accB.x + accB.y * accB.y + accB.z * accB.z + accB.w * accB.w);
        float n  = sqrtf(ss);
        float inv = 1.0f / fmaxf(n, 1e-12f);
        float4 oa = make_float4(accA.x * inv, accA.y * inv, accA.z * inv, accA.w * inv);
        float4 ob = make_float4(accB.x * inv, accB.y * inv, accB.z * inv, accB.w * inv);
        uint4 oh;
        *(__half2*)&oh.x = __floats2half2_rn(oa.x, oa.y);
        *(__half2*)&oh.y = __floats2half2_rn(oa.z, oa.w);
        *(__half2*)&oh.z = __floats2half2_rn(ob.x, ob.y);
        *(__half2*)&oh.w = __floats2half2_rn(ob.z, ob.w);

        if (gidx < NE) {
            *((uint4*)(next + (size_t)(NU + gidx) * C) + lane) = oh;
            if (lane == 0) fdst[gidx] = n / fmaxf((float)(end - start), 1.0f);
            if (hop_g == N_HOPS - 1) {
                float4* op = (float4*)(ent_out + (size_t)gidx * C) + lane * 2;
                op[0] = oa; op[1] = ob;
            }
        } else {
            int r = gidx - NE;
            // user-half of the state buffer is dead after the last hop
            if (r < NU && hop_g != N_HOPS - 1)
                *((uint4*)(next + (size_t)r * C) + lane) = oh;
            float4* rp = (float4*)(node_res + (size_t)r * C) + lane * 2;
            float4 a0, a1;
            if (hop0) {
                const float4* ip = (r < NU)
                    ? (const float4*)(user_emb + (size_t)r * C) + lane * 2
                    : (const float4*)(entity_emb + (size_t)(r - NU) * C) + lane * 2;
                a0 = ip[0]; a1 = ip[1];
            } else {
                a0 = rp[0]; a1 = rp[1];
            }
            a0.x += oa.x; a0.y += oa.y; a0.z += oa.z; a0.w += oa.w;
            a1.x += ob.x; a1.y += ob.y; a1.z += ob.z; a1.w += ob.w;
            rp[0] = a0; rp[1] = a1;
        }
    } else {
        // ---------------- im path (hop_m) ----------------
        if (!do_m) return;
        const __half* src  = buf_of(hop_m);
        const float*  fsrc = g_f + (hop_m & 1) * NE;
        int hop0 = (hop_m == 0);
        int u = gidx - NE - NN;

        float4 accA = make_float4(0.f, 0.f, 0.f, 0.f);
        float4 accB = make_float4(0.f, 0.f, 0.f, 0.f);
        int e = start;
        for (; e + 1 < end; e += 2) {
            int2 r0 = __ldg(g_rec2 + (e - EE2));
            int2 r1 = __ldg(g_rec2 + (e + 1 - EE2));
            float c0 = __int_as_float(r0.y) * __ldg(fsrc + r0.x);
            float c1 = __int_as_float(r1.y) * __ldg(fsrc + r1.x);
            uint4 h0 = *((const uint4*)(src + (size_t)(NU + r0.x) * C) + lane);
            uint4 h1 = *((const uint4*)(src + (size_t)(NU + r1.x) * C) + lane);
            F8 s0 = h8_to_f8(h0);
            F8 s1 = h8_to_f8(h1);
            accA.x += s0.a.x * c0 + s1.a.x * c1;
            accA.y += s0.a.y * c0 + s1.a.y * c1;
            accA.z += s0.a.z * c0 + s1.a.z * c1;
            accA.w += s0.a.w * c0 + s1.a.w * c1;
            accB.x += s0.b.x * c0 + s1.b.x * c1;
            accB.y += s0.b.y * c0 + s1.b.y * c1;
            accB.z += s0.b.z * c0 + s1.b.z * c1;
            accB.w += s0.b.w * c0 + s1.b.w * c1;
        }
        if (e < end) {
            int2 r0 = __ldg(g_rec2 + (e - EE2));
            float c0 = __int_as_float(r0.y) * __ldg(fsrc + r0.x);
            uint4 h0 = *((const uint4*)(src + (size_t)(NU + r0.x) * C) + lane);
            F8 s0 = h8_to_f8(h0);
            accA.x += s0.a.x * c0; accA.y += s0.a.y * c0;
            accA.z += s0.a.z * c0; accA.w += s0.a.w * c0;
            accB.x += s0.b.x * c0; accB.y += s0.b.y * c0;
            accB.z += s0.b.z * c0; accB.w += s0.b.w * c0;
        }

        float ss = grp_sum8(accA.x * accA.x + accA.y * accA.y + accA.z * accA.z + accA.w * accA.w
                          + accB.x * accB.x + accB.y * accB.y + accB.z * accB.z + accB.w * accB.w);
        float inv = 1.0f / fmaxf(sqrtf(ss), 1e-12f);
        float4* rp = (float4*)(user_res + (size_t)u * C) + lane * 2;
        float4 a0, a1;
        if (hop0) {
            const float4* ip = (const float4*)(user_emb + (size_t)u * C) + lane * 2;
            a0 = ip[0]; a1 = ip[1];
        } else {
            a0 = rp[0]; a1 = rp[1];
        }
        a0.x += accA.x * inv; a0.y += accA.y * inv;
        a0.z += accA.z * inv; a0.w += accA.w * inv;
        a1.x += accB.x * inv; a1.y += accB.y * inv;
        a1.z += accB.z * inv; a1.w += accB.w * inv;
        rp[0] = a0; rp[1] = a1;
    }
}

// ---------------------------------------------------------------------------
extern "C" void kernel_launch(void* const* d_in, const int* in_sizes, int n_in,
                              void* d_out, int out_size) {
    const float* user_emb     = (const float*)d_in[0];
    const float* entity_emb   = (const float*)d_in[1];
    const float* weight       = (const float*)d_in[2];
    const float* extra_weight = (const float*)d_in[3];
    const float* im_val       = (const float*)d_in[4];
    const int*   edge_index   = (const int*)d_in[5];
    const int*   edge_type    = (const int*)d_in[6];
    const int*   extra_eidx   = (const int*)d_in[7];
    const int*   extra_etype  = (const int*)d_in[8];
    const int*   im_row       = (const int*)d_in[9];
    const int*   im_col       = (const int*)d_in[10];

    const int E   = in_sizes[6];
    const int E2  = in_sizes[8];
    const int NNZ = in_sizes[4];
    const int total_rec = E + E2 + NNZ;
    const int EE2 = E + E2;

    float* out      = (float*)d_out;
    float* user_res = out;                      // [NU, C]
    float* ent_out  = out + (size_t)NU * C;     // [NE, C]
    float* node_res = out + (size_t)NN * C;     // [NN, C]

    zero_cnt_kernel<<<(NT / 4 + 255) / 256, 256>>>();
    init_hist_kernel<<<2048, 256>>>(user_emb, entity_emb, weight, extra_weight,
                                    edge_index, extra_eidx, im_row, E, E2, NNZ);
    chunk_sort_kernel<<<NCHUNK, 256>>>();
    scan_lb_kernel<<<NB, 256>>>(total_rec);
    fill_kernel<<<(total_rec + 1023) / 1024, 256>>>(edge_index, edge_type,
                                                    extra_eidx, extra_etype,
                                                    im_row, im_col, im_val, E, E2, NNZ);

    const int g_blocks  = ((NE + NN) * 8 + 255) / 256;   // gather-only
    const int gm_blocks = (NT * 8 + 255) / 256;          // gather + im
    const int m_blocks  = (NU * 8 + 255) / 256;          // im-only

    // g0 ; [im0 || g1] ; [im1 || g2] ; im2
    fused_kernel<<<g_blocks, 256>>>(0, 1, 0, 0, 0, EE2,
                                    user_emb, entity_emb, node_res, ent_out, user_res);
    fused_kernel<<<gm_blocks, 256>>>(1, 1, 0, 1, 0, EE2,
                                     user_emb, entity_emb, node_res, ent_out, user_res);
    fused_kernel<<<gm_blocks, 256>>>(2, 1, 1, 1, 0, EE2,
                                     user_emb, entity_emb, node_res, ent_out, user_res);
    fused_kernel<<<m_blocks, 256>>>(0, 0, 2, 1, NE + NN, EE2,
                                    user_emb, entity_emb, node_res, ent_out, user_res);
}